// round 4
// baseline (speedup 1.0000x reference)
#include <cuda_runtime.h>
#include <mma.h>
#include <math.h>

using namespace nvcuda;

#define BB 8
#define CC 128
#define HH 128
#define WW 128
#define NHH 4
#define HDD 32
#define SG2 256
#define HWP (HH*WW)      // 16384
#define NPIX (BB*HWP)    // 131072
#define KK2 25
#define SCALE 0.17677669529663687f   // 1/sqrt(32)

// ---- scratch (static device arrays; no runtime allocation) ----
static __device__ float g_q[(size_t)NPIX*CC];    // [(b*NH+h)*HW + ij]*HD + d
static __device__ float g_k[(size_t)NPIX*CC];
static __device__ float g_v[(size_t)NPIX*CC];
static __device__ float g_pwd[(size_t)NPIX*KK2]; // [p*25 + k]
static __device__ float g_agg[(size_t)NPIX*CC];  // [p*128 + c]

__device__ __forceinline__ float tf32r(float f) {
    unsigned r;
    asm("cvt.rna.tf32.f32 %0, %1;" : "=r"(r) : "f"(f));
    return __uint_as_float(r);
}
__device__ __forceinline__ float4 tf32r4(float4 v) {
    return make_float4(tf32r(v.x), tf32r(v.y), tf32r(v.z), tf32r(v.w));
}

// smem: bias[16][132] | A[.][132] | B[128][132]   (all tf32-prerounded)
#define GEMM_SMEM ((16*132 + 128*132 + 128*132)*4)

// ============================================================
// Kernel 1: QKV GEMM via WMMA tf32.
// A: x tile staged to smem ONCE, pre-converted (col_major m=pixel, k=chan).
// B: per-N-pass weight tile staged pre-converted (row_major k,n).
// Bias folded into accumulator init. D stored to q/k/v [pix][d], ld=32.
// ============================================================
__global__ void __launch_bounds__(256, 1)
k_qkv_wmma(const float* __restrict__ x, const float* __restrict__ w_qk,
           const float* __restrict__ b_qk, const float* __restrict__ w_v,
           const float* __restrict__ b_v)
{
    extern __shared__ float sm[];
    float* bias_s = sm;                      // [16][132]
    float* As     = sm + 16*132;             // [k=128][m=128] ld 132 (col_major)
    float* Bs     = sm + 16*132 + 128*132;   // [k=128][n=128] ld 132 (row_major)

    const int tid = threadIdx.x;
    const int wid = tid >> 5;
    const int wm  = wid & 3;        // m quarter  (32 pixels)
    const int wn  = wid >> 2;       // n half     (64 outputs)
    const int p0  = blockIdx.x * 128;
    const int b   = p0 / HWP;
    const int ij0 = p0 % HWP;
    const float* xb = x + (size_t)b*CC*HWP + ij0;

    // stage A once: As[k*132 + m] = tf32(x[b, k, ij0+m])
#pragma unroll
    for (int it = 0; it < 16; it++) {
        int idx = tid + it*256;            // 4096 float4
        int k = idx >> 5, m4 = idx & 31;
        *(float4*)(As + k*132 + m4*4) =
            tf32r4(*(const float4*)(xb + (size_t)k*HWP + m4*4));
    }

    for (int nt = 0; nt < 3; nt++) {
        __syncthreads();   // Bs/bias_s safe to overwrite (also covers As on nt=0)
#pragma unroll
        for (int it = 0; it < 16; it++) {
            int idx = tid + it*256;
            int k = idx >> 5, n4 = idx & 31;
            const float* src = (nt < 2) ? (w_qk + k*2*CC + nt*128 + n4*4)
                                        : (w_v  + k*CC  + n4*4);
            *(float4*)(Bs + k*132 + n4*4) = tf32r4(*(const float4*)src);
        }
        if (tid < 128) {
            float bv = (nt < 2) ? b_qk[nt*128 + tid] : b_v[tid];
#pragma unroll
            for (int r = 0; r < 16; r++) bias_s[r*132 + tid] = bv;
        }
        __syncthreads();

        wmma::fragment<wmma::accumulator, 16,16,8, float> acc[2][4];
#pragma unroll
        for (int mi = 0; mi < 2; mi++)
#pragma unroll
            for (int ni = 0; ni < 4; ni++)
                wmma::load_matrix_sync(acc[mi][ni], bias_s + wn*64 + ni*16,
                                       132, wmma::mem_row_major);

#pragma unroll
        for (int k0 = 0; k0 < CC; k0 += 8) {
            wmma::fragment<wmma::matrix_a, 16,16,8, wmma::precision::tf32,
                           wmma::col_major> a[2];
#pragma unroll
            for (int mi = 0; mi < 2; mi++)
                wmma::load_matrix_sync(a[mi], As + k0*132 + wm*32 + mi*16, 132);
            wmma::fragment<wmma::matrix_b, 16,16,8, wmma::precision::tf32,
                           wmma::row_major> bf[4];
#pragma unroll
            for (int ni = 0; ni < 4; ni++)
                wmma::load_matrix_sync(bf[ni], Bs + k0*132 + wn*64 + ni*16, 132);
#pragma unroll
            for (int mi = 0; mi < 2; mi++)
#pragma unroll
                for (int ni = 0; ni < 4; ni++)
                    wmma::mma_sync(acc[mi][ni], a[mi], bf[ni], acc[mi][ni]);
        }

        float* dstbase = (nt == 0) ? g_q : (nt == 1) ? g_k : g_v;
#pragma unroll
        for (int mi = 0; mi < 2; mi++)
#pragma unroll
            for (int ni = 0; ni < 4; ni++) {
                int n0 = wn*64 + ni*16;
                int head = n0 >> 5, d0 = n0 & 31;
                float* dst = dstbase +
                    ((size_t)(b*NHH + head)*HWP + ij0 + wm*32 + mi*16)*HDD + d0;
                wmma::store_matrix_sync(dst, acc[mi][ni], HDD, wmma::mem_row_major);
            }
    }
}

// ============================================================
// Kernel 2: pwd[p, k] = sum_s sims[p,s] * sims[p+off_k, s]
// ============================================================
__global__ void __launch_bounds__(256)
k_pwd(const float* __restrict__ sims)
{
    extern __shared__ float Ss[];  // [432 halo pixels][36]
    const int b  = blockIdx.z;
    const int i0 = blockIdx.y * 8;
    const int j0 = blockIdx.x * 32;
    const int tx = threadIdx.x, ty = threadIdx.y;
    const int tid = ty*32 + tx;
    const float* sb = sims + (size_t)b*HWP*SG2;

    float acc[KK2];
#pragma unroll
    for (int k=0;k<KK2;k++) acc[k] = 0.f;

    for (int scc = 0; scc < SG2; scc += 32) {
        __syncthreads();
        for (int idx = tid; idx < 432*8; idx += 256) {
            int pix = idx >> 3, v = idx & 7;
            int hr = pix / 36, hc = pix - hr*36;
            int gi = i0 - 2 + hr, gj = j0 - 2 + hc;
            float4 val = make_float4(0.f,0.f,0.f,0.f);
            if ((unsigned)gi < HH && (unsigned)gj < WW)
                val = *(const float4*)(sb + ((size_t)gi*WW + gj)*SG2 + scc + v*4);
            *(float4*)(Ss + pix*36 + v*4) = val;
        }
        __syncthreads();

        float own[32];
        const float* op = Ss + ((ty+2)*36 + (tx+2))*36;
#pragma unroll
        for (int v=0; v<8; v++) {
            float4 t = *(const float4*)(op + v*4);
            own[v*4]=t.x; own[v*4+1]=t.y; own[v*4+2]=t.z; own[v*4+3]=t.w;
        }
#pragma unroll
        for (int di=0; di<5; di++) {
#pragma unroll
            for (int dj=0; dj<5; dj++) {
                const float* np = Ss + ((ty+di)*36 + (tx+dj))*36;
                float s = 0.f;
#pragma unroll
                for (int v=0; v<8; v++) {
                    float4 t = *(const float4*)(np + v*4);
                    s = fmaf(own[v*4],   t.x, s);
                    s = fmaf(own[v*4+1], t.y, s);
                    s = fmaf(own[v*4+2], t.z, s);
                    s = fmaf(own[v*4+3], t.w, s);
                }
                acc[di*5+dj] += s;
            }
        }
    }
    const size_t p = (size_t)b*HWP + (size_t)(i0+ty)*WW + (j0+tx);
#pragma unroll
    for (int k=0;k<KK2;k++) g_pwd[p*KK2 + k] = acc[k];
}

// ============================================================
// Kernel 3: scores -> exp -> *pwd -> renorm -> V aggregation.
// ============================================================
__global__ void __launch_bounds__(256)
k_attn()
{
    extern __shared__ float Ts[];  // [432][36]
    const int bh = blockIdx.z;
    const int b  = bh >> 2;
    const int h  = bh & 3;
    const int i0 = blockIdx.y * 8;
    const int j0 = blockIdx.x * 32;
    const int tx = threadIdx.x, ty = threadIdx.y;
    const int tid = ty*32 + tx;
    const size_t headoff = (size_t)bh*HWP*HDD;
    const int ij = (i0+ty)*WW + (j0+tx);

    float q[32];
    {
        const float* qp = g_q + headoff + (size_t)ij*HDD;
#pragma unroll
        for (int v=0; v<8; v++) {
            float4 t = *(const float4*)(qp + v*4);
            q[v*4]=t.x; q[v*4+1]=t.y; q[v*4+2]=t.z; q[v*4+3]=t.w;
        }
    }

    const float* kb = g_k + headoff;
    for (int idx = tid; idx < 432*8; idx += 256) {
        int pix = idx >> 3, v = idx & 7;
        int hr = pix / 36, hc = pix - hr*36;
        int gi = i0 - 2 + hr, gj = j0 - 2 + hc;
        float4 val = make_float4(0.f,0.f,0.f,0.f);
        if ((unsigned)gi < HH && (unsigned)gj < WW)
            val = *(const float4*)(kb + (size_t)(gi*WW + gj)*HDD + v*4);
        *(float4*)(Ts + pix*36 + v*4) = val;
    }
    __syncthreads();

    float sc[KK2];
#pragma unroll
    for (int di=0; di<5; di++) {
#pragma unroll
        for (int dj=0; dj<5; dj++) {
            const float* np = Ts + ((ty+di)*36 + (tx+dj))*36;
            float s = 0.f;
#pragma unroll
            for (int v=0; v<8; v++) {
                float4 t = *(const float4*)(np + v*4);
                s = fmaf(q[v*4],   t.x, s);
                s = fmaf(q[v*4+1], t.y, s);
                s = fmaf(q[v*4+2], t.z, s);
                s = fmaf(q[v*4+3], t.w, s);
            }
            sc[di*5+dj] = s * SCALE;
        }
    }
    __syncthreads();

    const float* vb = g_v + headoff;
    for (int idx = tid; idx < 432*8; idx += 256) {
        int pix = idx >> 3, v = idx & 7;
        int hr = pix / 36, hc = pix - hr*36;
        int gi = i0 - 2 + hr, gj = j0 - 2 + hc;
        float4 val = make_float4(0.f,0.f,0.f,0.f);
        if ((unsigned)gi < HH && (unsigned)gj < WW)
            val = *(const float4*)(vb + (size_t)(gi*WW + gj)*HDD + v*4);
        *(float4*)(Ts + pix*36 + v*4) = val;
    }

    float m = sc[0];
#pragma unroll
    for (int k=1;k<KK2;k++) m = fmaxf(m, sc[k]);
    const float* pw = g_pwd + ((size_t)b*HWP + ij)*KK2;
    float w[KK2]; float ssum = 0.f;
#pragma unroll
    for (int k=0;k<KK2;k++) { w[k] = __expf(sc[k]-m) * pw[k]; ssum += w[k]; }
    const float inv = 1.f / fmaxf(ssum, 1e-30f);

    __syncthreads();

    float out[32];
#pragma unroll
    for (int v=0;v<32;v++) out[v] = 0.f;
#pragma unroll
    for (int di=0; di<5; di++) {
#pragma unroll
        for (int dj=0; dj<5; dj++) {
            float wk = w[di*5+dj] * inv;
            const float* np = Ts + ((ty+di)*36 + (tx+dj))*36;
#pragma unroll
            for (int v=0; v<8; v++) {
                float4 t = *(const float4*)(np + v*4);
                out[v*4]   = fmaf(wk, t.x, out[v*4]);
                out[v*4+1] = fmaf(wk, t.y, out[v*4+1]);
                out[v*4+2] = fmaf(wk, t.z, out[v*4+2]);
                out[v*4+3] = fmaf(wk, t.w, out[v*4+3]);
            }
        }
    }
    float* ag = g_agg + ((size_t)b*HWP + ij)*CC + h*HDD;
#pragma unroll
    for (int v=0; v<8; v++)
        *(float4*)(ag + v*4) = make_float4(out[v*4], out[v*4+1],
                                           out[v*4+2], out[v*4+3]);
}

// ============================================================
// Kernel 4: proj GEMM via WMMA tf32, A+B staged pre-converted in smem,
// free BCHW transpose on store (col_major, ld=HWP).
// ============================================================
__global__ void __launch_bounds__(256, 1)
k_proj_wmma(const float* __restrict__ w_proj, const float* __restrict__ b_proj,
            float* __restrict__ out)
{
    extern __shared__ float sm[];
    float* bias_s = sm;                      // [16][132]
    float* As     = sm + 16*132;             // [m=128][k=128] ld 132 (row_major)
    float* Bs     = sm + 16*132 + 128*132;   // [k=128][n=128] ld 132 (row_major)

    const int tid = threadIdx.x;
    const int wid = tid >> 5;
    const int wm  = wid & 3;
    const int wn  = wid >> 2;
    const int p0  = blockIdx.x * 128;
    const int b   = p0 / HWP;
    const int ij0 = p0 % HWP;

    const float* ab = g_agg + (size_t)p0 * CC;
#pragma unroll
    for (int it = 0; it < 16; it++) {
        int idx = tid + it*256;
        int m = idx >> 5, k4 = idx & 31;
        *(float4*)(As + m*132 + k4*4) =
            tf32r4(*(const float4*)(ab + (size_t)m*CC + k4*4));
    }
#pragma unroll
    for (int it = 0; it < 16; it++) {
        int idx = tid + it*256;
        int k = idx >> 5, n4 = idx & 31;
        *(float4*)(Bs + k*132 + n4*4) =
            tf32r4(*(const float4*)(w_proj + k*CC + n4*4));
    }
    if (tid < 128) {
        float bv = b_proj[tid];
#pragma unroll
        for (int r = 0; r < 16; r++) bias_s[r*132 + tid] = bv;
    }
    __syncthreads();

    wmma::fragment<wmma::accumulator, 16,16,8, float> acc[2][4];
#pragma unroll
    for (int mi = 0; mi < 2; mi++)
#pragma unroll
        for (int ni = 0; ni < 4; ni++)
            wmma::load_matrix_sync(acc[mi][ni], bias_s + wn*64 + ni*16,
                                   132, wmma::mem_row_major);

#pragma unroll
    for (int k0 = 0; k0 < CC; k0 += 8) {
        wmma::fragment<wmma::matrix_a, 16,16,8, wmma::precision::tf32,
                       wmma::row_major> a[2];
#pragma unroll
        for (int mi = 0; mi < 2; mi++)
            wmma::load_matrix_sync(a[mi], As + (wm*32 + mi*16)*132 + k0, 132);
        wmma::fragment<wmma::matrix_b, 16,16,8, wmma::precision::tf32,
                       wmma::row_major> bf[4];
#pragma unroll
        for (int ni = 0; ni < 4; ni++)
            wmma::load_matrix_sync(bf[ni], Bs + k0*132 + wn*64 + ni*16, 132);
#pragma unroll
        for (int mi = 0; mi < 2; mi++)
#pragma unroll
            for (int ni = 0; ni < 4; ni++)
                wmma::mma_sync(acc[mi][ni], a[mi], bf[ni], acc[mi][ni]);
    }

    float* ob = out + (size_t)b*CC*HWP + ij0;
#pragma unroll
    for (int mi = 0; mi < 2; mi++)
#pragma unroll
        for (int ni = 0; ni < 4; ni++) {
            int n0 = wn*64 + ni*16;
            int m0 = wm*32 + mi*16;
            wmma::store_matrix_sync(ob + (size_t)n0*HWP + m0, acc[mi][ni],
                                    HWP, wmma::mem_col_major);
        }
}

// ============================================================
extern "C" void kernel_launch(void* const* d_in, const int* in_sizes, int n_in,
                              void* d_out, int out_size)
{
    const float* x      = (const float*)d_in[0];
    const float* sims   = (const float*)d_in[1];
    const float* w_qk   = (const float*)d_in[2];
    const float* b_qk   = (const float*)d_in[3];
    const float* w_v    = (const float*)d_in[4];
    const float* b_v    = (const float*)d_in[5];
    const float* w_proj = (const float*)d_in[6];
    const float* b_proj = (const float*)d_in[7];
    float* out = (float*)d_out;

    cudaFuncSetAttribute(k_qkv_wmma,  cudaFuncAttributeMaxDynamicSharedMemorySize, GEMM_SMEM);
    cudaFuncSetAttribute(k_pwd,       cudaFuncAttributeMaxDynamicSharedMemorySize, 432*36*4);
    cudaFuncSetAttribute(k_attn,      cudaFuncAttributeMaxDynamicSharedMemorySize, 432*36*4);
    cudaFuncSetAttribute(k_proj_wmma, cudaFuncAttributeMaxDynamicSharedMemorySize, GEMM_SMEM);

    k_qkv_wmma <<<NPIX/128, 256, GEMM_SMEM>>>(x, w_qk, b_qk, w_v, b_v);
    k_pwd      <<<dim3(WW/32, HH/8, BB),     dim3(32,8), 432*36*4>>>(sims);
    k_attn     <<<dim3(WW/32, HH/8, BB*NHH), dim3(32,8), 432*36*4>>>();
    k_proj_wmma<<<NPIX/128, 256, GEMM_SMEM>>>(w_proj, b_proj, out);
}